// round 14
// baseline (speedup 1.0000x reference)
#include <cuda_runtime.h>
#include <cuda_fp16.h>

#define L1D 16
#define IN_DIM 128
#define MAXN 65536
#define ZST 132      // padded smem row stride in node MLP
#define NPB 32       // nodes per block in node_mlp
#define WROW 40      // combined weight row stride in halves (32 data + 8 pad)

// Scratch: node hidden activations in fp16 (allowed: __device__ globals)
__device__ __align__(16) __half g_h1h[MAXN * L1D];
__device__ __align__(16) __half g_h2h[MAXN * L1D];

// packed f32x2 fma: d = a*b + d
__device__ __forceinline__ void fma_f32x2(unsigned long long& d,
                                          unsigned long long a,
                                          unsigned long long b) {
    asm("fma.rn.f32x2 %0, %1, %2, %0;" : "+l"(d) : "l"(a), "l"(b));
}
__device__ __forceinline__ float unpack_sum(unsigned long long v) {
    float lo = __uint_as_float((unsigned)(v & 0xFFFFFFFFu));
    float hi = __uint_as_float((unsigned)(v >> 32));
    return lo + hi;
}

// ---------------------------------------------------------------------------
// Kernel 1: per-node tiny MLP.  h1 = relu(z @ w1_l1), h2 = relu(z @ w2_l1)
// Block = 128 threads, 32 nodes. fp32 accumulate (f32x2), fp16 store.
// (Byte-identical to the last-measured-good round.)
// ---------------------------------------------------------------------------
__global__ __launch_bounds__(128) void node_mlp_kernel(
    const float* __restrict__ z,
    const float* __restrict__ w1,
    const float* __restrict__ w2,
    int n_nodes)
{
    __shared__ float zs[NPB * ZST];      // 16896 B
    __shared__ float w1T[L1D * ZST];     // [col][k], 8448 B
    __shared__ float w2T[L1D * ZST];

    const int tid = threadIdx.x;
    const int nbase = blockIdx.x * NPB;

    for (int i = tid; i < IN_DIM * L1D; i += 128) {
        int k = i >> 4, c = i & 15;
        w1T[c * ZST + k] = w1[i];
        w2T[c * ZST + k] = w2[i];
    }
    {
        const float4* z4 = (const float4*)(z + (size_t)nbase * IN_DIM);
        int nval = n_nodes - nbase; if (nval > NPB) nval = NPB;
        for (int i = tid; i < nval * (IN_DIM / 4); i += 128) {
            int r = i >> 5, q = i & 31;
            *(float4*)(zs + r * ZST + q * 4) = z4[i];
        }
    }
    __syncthreads();

    const int col  = tid & 15;
    const int slot = (tid >> 4) & 1;
    const int warp = tid >> 5;
    const int nloc0 = warp * 8 + slot * 4;

    unsigned long long a1[4][2] = {}, a2[4][2] = {};

    #pragma unroll 8
    for (int k = 0; k < IN_DIM; k += 4) {
        ulonglong2 wa = *(const ulonglong2*)(w1T + col * ZST + k);
        ulonglong2 wb = *(const ulonglong2*)(w2T + col * ZST + k);
        #pragma unroll
        for (int j = 0; j < 4; j++) {
            ulonglong2 zv = *(const ulonglong2*)(zs + (nloc0 + j) * ZST + k);
            fma_f32x2(a1[j][0], zv.x, wa.x);
            fma_f32x2(a1[j][1], zv.y, wa.y);
            fma_f32x2(a2[j][0], zv.x, wb.x);
            fma_f32x2(a2[j][1], zv.y, wb.y);
        }
    }

    #pragma unroll
    for (int j = 0; j < 4; j++) {
        int node = nbase + nloc0 + j;
        if (node < n_nodes) {
            float v1 = fmaxf(unpack_sum(a1[j][0]) + unpack_sum(a1[j][1]), 0.f);
            float v2 = fmaxf(unpack_sum(a2[j][0]) + unpack_sum(a2[j][1]), 0.f);
            g_h1h[node * L1D + col] = __float2half_rn(v1);
            g_h2h[node * L1D + col] = __float2half_rn(v2);
        }
    }
}

// ---------------------------------------------------------------------------
// Kernel 2: per-edge scoring, 4 lanes per edge, TWO consecutive edge pairs
// (4 edges) per group-iteration so each thread keeps 4 independent gathers
// in flight. Role-split vector index loads; combined fp16 weight rows;
// paired float2 stores.
// ---------------------------------------------------------------------------
__global__ __launch_bounds__(256) void edge_kernel(
    const float* __restrict__ w1_l2,
    const float* __restrict__ w2_l2,
    const void* __restrict__ ei,
    const void* __restrict__ et,
    float* __restrict__ out,
    int n_edges, int n_etype)
{
    extern __shared__ __half wch[];   // [n_etype][WROW]
    __shared__ int s_is64;

    if (threadIdx.x < 32) {
        unsigned v = ((const unsigned*)ei)[2 * threadIdx.x + 1];
        unsigned any = __ballot_sync(0xFFFFFFFFu, v != 0u);
        if (threadIdx.x == 0) s_is64 = (any == 0u) ? 1 : 0;
    }
    // stage combined fp16 rows: chunk i = (t, q): q<2 from w1, else w2
    for (int i = threadIdx.x; i < n_etype * 4; i += blockDim.x) {
        int t = i >> 2, q = i & 3;
        const float4* src = (q < 2) ? (const float4*)w1_l2 : (const float4*)w2_l2;
        int qq = q & 1;
        float4 fa = src[t * 4 + qq * 2];
        float4 fb = src[t * 4 + qq * 2 + 1];
        __half2 h0 = __float22half2_rn(make_float2(fa.x, fa.y));
        __half2 h1 = __float22half2_rn(make_float2(fa.z, fa.w));
        __half2 h2 = __float22half2_rn(make_float2(fb.x, fb.y));
        __half2 h3 = __float22half2_rn(make_float2(fb.z, fb.w));
        uint4 pk = make_uint4(*(unsigned*)&h0, *(unsigned*)&h1,
                              *(unsigned*)&h2, *(unsigned*)&h3);
        *(uint4*)(wch + t * WROW + q * 8) = pk;
    }
    __syncthreads();

    const int is64 = s_is64;
    const bool even = (n_edges & 1) == 0;
    const int sub = threadIdx.x & 3;
    const int lane_group = (threadIdx.x >> 2) & 7;
    const int group0 = (blockIdx.x * blockDim.x + threadIdx.x) >> 2;
    const int G = (gridDim.x * blockDim.x) >> 2;
    const int warp_base0 = group0 - lane_group;
    const int npairs = (n_edges + 1) >> 1;
    const int pmax = npairs - 1;
    const int emax = n_edges - 1;

    const __half* htab = (sub < 2) ? g_h1h : g_h2h;
    const int hq = (sub & 1) * 8;
    const size_t noff = (sub < 2) ? 0 : (size_t)n_edges;

    const long long* p64 = (const long long*)ei + noff;
    const int*       p32 = (const int*)ei + noff;
    const long long* t64 = (const long long*)et;
    const int*       t32 = (const int*)et;

    for (int base = warp_base0; base < npairs; base += 2 * G) {
        int ppA = base + lane_group;
        int ppB = base + G + lane_group;
        int pcA = ppA < npairs ? ppA : pmax;
        int pcB = ppB < npairs ? ppB : pmax;
        int eA = 2 * pcA;
        int eB = 2 * pcB;

        int n0, n1, n2, n3, t0, t1, t2, t3;
        if (is64) {
            if (even) {
                longlong2 nvA = *(const longlong2*)(p64 + eA);
                longlong2 nvB = *(const longlong2*)(p64 + eB);
                longlong2 tvA = *(const longlong2*)(t64 + eA);
                longlong2 tvB = *(const longlong2*)(t64 + eB);
                n0 = (int)nvA.x; n1 = (int)nvA.y;
                n2 = (int)nvB.x; n3 = (int)nvB.y;
                t0 = (int)tvA.x; t1 = (int)tvA.y;
                t2 = (int)tvB.x; t3 = (int)tvB.y;
            } else {
                int eA1 = (eA + 1 < n_edges) ? eA + 1 : emax;
                int eB1 = (eB + 1 < n_edges) ? eB + 1 : emax;
                n0 = (int)__ldg(p64 + eA);  n1 = (int)__ldg(p64 + eA1);
                n2 = (int)__ldg(p64 + eB);  n3 = (int)__ldg(p64 + eB1);
                t0 = (int)__ldg(t64 + eA);  t1 = (int)__ldg(t64 + eA1);
                t2 = (int)__ldg(t64 + eB);  t3 = (int)__ldg(t64 + eB1);
            }
        } else {
            if (even) {
                int2 nvA = *(const int2*)(p32 + eA);
                int2 nvB = *(const int2*)(p32 + eB);
                int2 tvA = *(const int2*)(t32 + eA);
                int2 tvB = *(const int2*)(t32 + eB);
                n0 = nvA.x; n1 = nvA.y; n2 = nvB.x; n3 = nvB.y;
                t0 = tvA.x; t1 = tvA.y; t2 = tvB.x; t3 = tvB.y;
            } else {
                int eA1 = (eA + 1 < n_edges) ? eA + 1 : emax;
                int eB1 = (eB + 1 < n_edges) ? eB + 1 : emax;
                n0 = __ldg(p32 + eA);  n1 = __ldg(p32 + eA1);
                n2 = __ldg(p32 + eB);  n3 = __ldg(p32 + eB1);
                t0 = __ldg(t32 + eA);  t1 = __ldg(t32 + eA1);
                t2 = __ldg(t32 + eB);  t3 = __ldg(t32 + eB1);
            }
        }

        // 4 independent gathers in flight
        uint4 hv0 = *(const uint4*)(htab + n0 * L1D + hq);
        uint4 hv1 = *(const uint4*)(htab + n1 * L1D + hq);
        uint4 hv2 = *(const uint4*)(htab + n2 * L1D + hq);
        uint4 hv3 = *(const uint4*)(htab + n3 * L1D + hq);
        uint4 wv0 = *(const uint4*)(wch + t0 * WROW + sub * 8);
        uint4 wv1 = *(const uint4*)(wch + t1 * WROW + sub * 8);
        uint4 wv2 = *(const uint4*)(wch + t2 * WROW + sub * 8);
        uint4 wv3 = *(const uint4*)(wch + t3 * WROW + sub * 8);

        float acc0 = 0.f, acc1 = 0.f, acc2 = 0.f, acc3 = 0.f;
        {
            const unsigned* hp0 = (const unsigned*)&hv0;
            const unsigned* wp0 = (const unsigned*)&wv0;
            const unsigned* hp1 = (const unsigned*)&hv1;
            const unsigned* wp1 = (const unsigned*)&wv1;
            const unsigned* hp2 = (const unsigned*)&hv2;
            const unsigned* wp2 = (const unsigned*)&wv2;
            const unsigned* hp3 = (const unsigned*)&hv3;
            const unsigned* wp3 = (const unsigned*)&wv3;
            #pragma unroll
            for (int k = 0; k < 4; k++) {
                float2 ha = __half22float2(*(const __half2*)(hp0 + k));
                float2 wa = __half22float2(*(const __half2*)(wp0 + k));
                acc0 = fmaf(ha.x, wa.x, acc0);
                acc0 = fmaf(ha.y, wa.y, acc0);
                float2 hb = __half22float2(*(const __half2*)(hp1 + k));
                float2 wb = __half22float2(*(const __half2*)(wp1 + k));
                acc1 = fmaf(hb.x, wb.x, acc1);
                acc1 = fmaf(hb.y, wb.y, acc1);
                float2 hc = __half22float2(*(const __half2*)(hp2 + k));
                float2 wc = __half22float2(*(const __half2*)(wp2 + k));
                acc2 = fmaf(hc.x, wc.x, acc2);
                acc2 = fmaf(hc.y, wc.y, acc2);
                float2 hd = __half22float2(*(const __half2*)(hp3 + k));
                float2 wd = __half22float2(*(const __half2*)(wp3 + k));
                acc3 = fmaf(hd.x, wd.x, acc3);
                acc3 = fmaf(hd.y, wd.y, acc3);
            }
        }

        acc0 += __shfl_xor_sync(0xFFFFFFFFu, acc0, 1);
        acc1 += __shfl_xor_sync(0xFFFFFFFFu, acc1, 1);
        acc2 += __shfl_xor_sync(0xFFFFFFFFu, acc2, 1);
        acc3 += __shfl_xor_sync(0xFFFFFFFFu, acc3, 1);
        acc0 += __shfl_xor_sync(0xFFFFFFFFu, acc0, 2);
        acc1 += __shfl_xor_sync(0xFFFFFFFFu, acc1, 2);
        acc2 += __shfl_xor_sync(0xFFFFFFFFu, acc2, 2);
        acc3 += __shfl_xor_sync(0xFFFFFFFFu, acc3, 2);

        if (sub == 0) {
            float o0 = 1.f / (1.f + __expf(-acc0));
            float o1 = 1.f / (1.f + __expf(-acc1));
            float o2 = 1.f / (1.f + __expf(-acc2));
            float o3 = 1.f / (1.f + __expf(-acc3));
            if (eA + 1 < n_edges) *(float2*)(out + eA) = make_float2(o0, o1);
            else                   out[eA] = o0;
            if (eB + 1 < n_edges) *(float2*)(out + eB) = make_float2(o2, o3);
            else                   out[eB] = o2;
        }
    }
}

// ---------------------------------------------------------------------------
// Launch. Inputs (metadata order): z, w1_l1, w1_l2, w2_l1, w2_l2,
// edge_index [2,E], edge_type [E].  Output: float32 [E].
// ---------------------------------------------------------------------------
extern "C" void kernel_launch(void* const* d_in, const int* in_sizes, int n_in,
                              void* d_out, int out_size) {
    const float* z     = (const float*)d_in[0];
    const float* w1_l1 = (const float*)d_in[1];
    const float* w1_l2 = (const float*)d_in[2];
    const float* w2_l1 = (const float*)d_in[3];
    const float* w2_l2 = (const float*)d_in[4];
    const void*  ei    = d_in[5];
    const void*  et    = d_in[6];
    float* out = (float*)d_out;

    int n_nodes = in_sizes[0] / IN_DIM;
    int n_etype = in_sizes[2] / L1D;
    int n_edges = out_size;

    int nb1 = (n_nodes + NPB - 1) / NPB;
    node_mlp_kernel<<<nb1, 128>>>(z, w1_l1, w2_l1, n_nodes);

    size_t smem2 = (size_t)n_etype * WROW * sizeof(__half);
    edge_kernel<<<1036, 256, smem2>>>(w1_l2, w2_l2, ei, et, out, n_edges, n_etype);
}